// round 4
// baseline (speedup 1.0000x reference)
#include <cuda_runtime.h>
#include <math.h>
#include <stdint.h>

#define BB 16
#define DD 2048
#define NH 32
#define NKV 8
#define HDIM 64
#define GRP 4
#define TSEQ 4096
#define HIDDEN 5632
#define KVD 512   // NKV*HDIM

// ---------------- scratch (device globals; no allocation allowed) ----------------
__device__ float g_xn[BB * DD];
__device__ float g_q[BB * DD];
__device__ float g_k[BB * KVD];
__device__ float g_v[BB * KVD];
__device__ float g_attn[BB * DD];
__device__ float g_h[BB * DD];
__device__ float g_hn[BB * DD];
__device__ float g_ff1[BB * HIDDEN];
__device__ float g_scores[BB * NKV * GRP * TSEQ];   // 8 MB

// ---------------- helpers ----------------
__device__ __forceinline__ float warp_sum(float v) {
    v += __shfl_down_sync(0xffffffffu, v, 16);
    v += __shfl_down_sync(0xffffffffu, v, 8);
    v += __shfl_down_sync(0xffffffffu, v, 4);
    v += __shfl_down_sync(0xffffffffu, v, 2);
    v += __shfl_down_sync(0xffffffffu, v, 1);
    return v;
}

// Accumulate acc[b][j] += dot(A[b,:], W[o0+j,:]) over K, warp-cooperative.
__device__ __forceinline__ void gemv_core(const float* __restrict__ A,
                                          const float* __restrict__ W,
                                          int o0, int K, int lane,
                                          float acc[16][4]) {
    const float4* w0 = (const float4*)(W + (size_t)(o0 + 0) * K);
    const float4* w1 = (const float4*)(W + (size_t)(o0 + 1) * K);
    const float4* w2 = (const float4*)(W + (size_t)(o0 + 2) * K);
    const float4* w3 = (const float4*)(W + (size_t)(o0 + 3) * K);
    int K4 = K >> 2;
    for (int c = lane; c < K4; c += 32) {
        float4 a0 = w0[c], a1 = w1[c], a2 = w2[c], a3 = w3[c];
#pragma unroll
        for (int b = 0; b < 16; b++) {
            float4 xv = ((const float4*)(A + (size_t)b * K))[c];
            acc[b][0] += a0.x * xv.x + a0.y * xv.y + a0.z * xv.z + a0.w * xv.w;
            acc[b][1] += a1.x * xv.x + a1.y * xv.y + a1.z * xv.z + a1.w * xv.w;
            acc[b][2] += a2.x * xv.x + a2.y * xv.y + a2.z * xv.z + a2.w * xv.w;
            acc[b][3] += a3.x * xv.x + a3.y * xv.y + a3.z * xv.z + a3.w * xv.w;
        }
    }
}

// ---------------- kernels ----------------
// rmsnorm variant 1: input from harness pointer x -> g_xn  (device globals
// referenced ONLY inside device code; passing __device__ symbols as host-side
// kernel args silently writes to the host shadow on GB300/ATS).
__global__ void rmsnorm_x_kernel(const float* __restrict__ x,
                                 const float* __restrict__ w) {
    int b = blockIdx.x;
    const float* xr = x + (size_t)b * DD;
    float s = 0.f;
    for (int i = threadIdx.x; i < DD; i += 256) { float v = xr[i]; s += v * v; }
    for (int off = 16; off; off >>= 1) s += __shfl_xor_sync(0xffffffffu, s, off);
    __shared__ float red[8];
    int lane = threadIdx.x & 31, wid = threadIdx.x >> 5;
    if (lane == 0) red[wid] = s;
    __syncthreads();
    if (threadIdx.x == 0) {
        float t = 0.f;
#pragma unroll
        for (int i = 0; i < 8; i++) t += red[i];
        red[0] = rsqrtf(t * (1.0f / DD) + 1e-6f);
    }
    __syncthreads();
    float inv = red[0];
    float* orow = g_xn + (size_t)b * DD;
    for (int i = threadIdx.x; i < DD; i += 256) orow[i] = xr[i] * inv * w[i];
}

// rmsnorm variant 2: g_h -> g_hn
__global__ void rmsnorm_h_kernel(const float* __restrict__ w) {
    int b = blockIdx.x;
    const float* xr = g_h + (size_t)b * DD;
    float s = 0.f;
    for (int i = threadIdx.x; i < DD; i += 256) { float v = xr[i]; s += v * v; }
    for (int off = 16; off; off >>= 1) s += __shfl_xor_sync(0xffffffffu, s, off);
    __shared__ float red[8];
    int lane = threadIdx.x & 31, wid = threadIdx.x >> 5;
    if (lane == 0) red[wid] = s;
    __syncthreads();
    if (threadIdx.x == 0) {
        float t = 0.f;
#pragma unroll
        for (int i = 0; i < 8; i++) t += red[i];
        red[0] = rsqrtf(t * (1.0f / DD) + 1e-6f);
    }
    __syncthreads();
    float inv = red[0];
    float* orow = g_hn + (size_t)b * DD;
    for (int i = threadIdx.x; i < DD; i += 256) orow[i] = xr[i] * inv * w[i];
}

__global__ __launch_bounds__(128, 4) void gemv_qkv_kernel(
    const float* __restrict__ wq, const float* __restrict__ wk,
    const float* __restrict__ wv) {
    int lane = threadIdx.x & 31, w = threadIdx.x >> 5;
    int o = blockIdx.x * 16 + w * 4;
    const float* W; float* C; int oo, cst;
    if (o < 2048)      { W = wq; C = g_q; oo = o;        cst = DD;  }
    else if (o < 2560) { W = wk; C = g_k; oo = o - 2048; cst = KVD; }
    else               { W = wv; C = g_v; oo = o - 2560; cst = KVD; }
    float acc[16][4];
#pragma unroll
    for (int b = 0; b < 16; b++) { acc[b][0]=0;acc[b][1]=0;acc[b][2]=0;acc[b][3]=0; }
    gemv_core(g_xn, W, oo, DD, lane, acc);
#pragma unroll
    for (int b = 0; b < 16; b++)
#pragma unroll
        for (int j = 0; j < 4; j++) {
            float v = warp_sum(acc[b][j]);
            if (lane == 0) C[(size_t)b * cst + oo + j] = v;
        }
}

__global__ void rope_kernel(const float* __restrict__ cosv,
                            const float* __restrict__ sinv) {
    int idx = blockIdx.x * 256 + threadIdx.x;
    if (idx >= BB * 48 * 32) return;
    int b = idx / (48 * 32);
    int r = idx % (48 * 32);
    int head = r >> 5;
    int i = r & 31;
    float c = cosv[i], s = sinv[i];
    float* ptr;
    if (head < 32)      ptr = g_q + (size_t)b * DD  + head * 64;
    else if (head < 40) ptr = g_k + (size_t)b * KVD + (head - 32) * 64;
    else                ptr = g_v + (size_t)b * KVD + (head - 40) * 64;
    float x0 = ptr[2 * i], x1 = ptr[2 * i + 1];
    ptr[2 * i]     = x0 * c - x1 * s;
    ptr[2 * i + 1] = x0 * s + x1 * c;
}

__global__ __launch_bounds__(256) void attn_kernel(
    const float* __restrict__ cache_k, const float* __restrict__ cache_v) {
    int pair = blockIdx.x;             // b*8 + kv
    int b = pair >> 3, kv = pair & 7;
    int tid = threadIdx.x, lane = tid & 31, wid = tid >> 5;

    __shared__ float q_s[4][64];
    __shared__ float red[4][8];
    __shared__ float m_s[4], inv_s[4];

    { // load + scale q
        int g = tid >> 6, d = tid & 63;
        q_s[g][d] = g_q[(size_t)b * DD + (kv * 4 + g) * 64 + d] * 0.125f;
    }
    __syncthreads();

    int c = lane & 3, p = lane >> 2;
    float qr[4][16];
#pragma unroll
    for (int g = 0; g < 4; g++)
#pragma unroll
        for (int j = 0; j < 16; j++) qr[g][j] = q_s[g][c * 16 + j];

    float* sc = g_scores + (size_t)pair * 4 * TSEQ;
    const float* kbase = cache_k + ((size_t)b * TSEQ * NKV + kv) * HDIM;
    const float* knew  = g_k + (size_t)(b * NKV + kv) * HDIM;

    // phase 1: scores[g][t]
    for (int t0 = wid * 8; t0 < TSEQ; t0 += 64) {
        int t = t0 + p;
        const float* krow = (t < TSEQ - 1) ? (kbase + (size_t)t * KVD) : knew;
        const float4* k4 = (const float4*)(krow + c * 16);
        float4 k0 = k4[0], k1 = k4[1], k2 = k4[2], k3 = k4[3];
        float kv16[16] = {k0.x,k0.y,k0.z,k0.w, k1.x,k1.y,k1.z,k1.w,
                          k2.x,k2.y,k2.z,k2.w, k3.x,k3.y,k3.z,k3.w};
        float s[4];
#pragma unroll
        for (int g = 0; g < 4; g++) {
            float acc = 0.f;
#pragma unroll
            for (int j = 0; j < 16; j++) acc += qr[g][j] * kv16[j];
            s[g] = acc;
        }
#pragma unroll
        for (int g = 0; g < 4; g++) {
            s[g] += __shfl_xor_sync(0xffffffffu, s[g], 1);
            s[g] += __shfl_xor_sync(0xffffffffu, s[g], 2);
        }
        if (c == 0) {
#pragma unroll
            for (int g = 0; g < 4; g++) sc[g * TSEQ + t] = s[g];
        }
    }
    __syncthreads();

    // phase 2: softmax (max, exp, sum)
    float lm[4] = {-1e30f, -1e30f, -1e30f, -1e30f};
    for (int i = tid; i < TSEQ; i += 256) {
#pragma unroll
        for (int g = 0; g < 4; g++) lm[g] = fmaxf(lm[g], sc[g * TSEQ + i]);
    }
#pragma unroll
    for (int g = 0; g < 4; g++) {
        for (int off = 16; off; off >>= 1)
            lm[g] = fmaxf(lm[g], __shfl_xor_sync(0xffffffffu, lm[g], off));
        if (lane == 0) red[g][wid] = lm[g];
    }
    __syncthreads();
    if (tid < 4) {
        float m = -1e30f;
#pragma unroll
        for (int w = 0; w < 8; w++) m = fmaxf(m, red[tid][w]);
        m_s[tid] = m;
    }
    __syncthreads();
    float ls[4] = {0.f, 0.f, 0.f, 0.f};
    for (int i = tid; i < TSEQ; i += 256) {
#pragma unroll
        for (int g = 0; g < 4; g++) {
            float e = __expf(sc[g * TSEQ + i] - m_s[g]);
            sc[g * TSEQ + i] = e;
            ls[g] += e;
        }
    }
#pragma unroll
    for (int g = 0; g < 4; g++) {
        ls[g] = warp_sum(ls[g]);
        if (lane == 0) red[g][wid] = ls[g];
    }
    __syncthreads();
    if (tid < 4) {
        float s = 0.f;
#pragma unroll
        for (int w = 0; w < 8; w++) s += red[tid][w];
        inv_s[tid] = 1.0f / s;
    }
    __syncthreads();

    // phase 3: PV
    int g = tid >> 6, d = tid & 63;
    const float* vbase = cache_v + ((size_t)b * TSEQ * NKV + kv) * HDIM + d;
    const float* pg = sc + (size_t)g * TSEQ;
    float a0 = 0.f, a1 = 0.f, a2 = 0.f, a3 = 0.f;
    for (int t = 0; t < TSEQ - 4; t += 4) {
        float4 pv = *(const float4*)(pg + t);
        a0 += pv.x * vbase[(size_t)(t + 0) * KVD];
        a1 += pv.y * vbase[(size_t)(t + 1) * KVD];
        a2 += pv.z * vbase[(size_t)(t + 2) * KVD];
        a3 += pv.w * vbase[(size_t)(t + 3) * KVD];
    }
    {
        int t = TSEQ - 4;
        float4 pv = *(const float4*)(pg + t);
        a0 += pv.x * vbase[(size_t)(t + 0) * KVD];
        a1 += pv.y * vbase[(size_t)(t + 1) * KVD];
        a2 += pv.z * vbase[(size_t)(t + 2) * KVD];
        a3 += pv.w * g_v[(size_t)(b * NKV + kv) * HDIM + d];   // new token V
    }
    float r = (a0 + a1 + a2 + a3) * inv_s[g];
    g_attn[(size_t)b * DD + (kv * 4 + g) * 64 + d] = r;
}

__global__ __launch_bounds__(128, 4) void gemv_wo_kernel(
    const float* __restrict__ wo, const float* __restrict__ x) {
    int lane = threadIdx.x & 31, w = threadIdx.x >> 5;
    int o = blockIdx.x * 16 + w * 4;
    float acc[16][4];
#pragma unroll
    for (int b = 0; b < 16; b++) { acc[b][0]=0;acc[b][1]=0;acc[b][2]=0;acc[b][3]=0; }
    gemv_core(g_attn, wo, o, DD, lane, acc);
#pragma unroll
    for (int b = 0; b < 16; b++)
#pragma unroll
        for (int j = 0; j < 4; j++) {
            float v = warp_sum(acc[b][j]);
            if (lane == 0) g_h[(size_t)b * DD + o + j] = v + x[(size_t)b * DD + o + j];
        }
}

__global__ __launch_bounds__(128, 4) void gemv_w1_kernel(const float* __restrict__ w1) {
    int lane = threadIdx.x & 31, w = threadIdx.x >> 5;
    int o = blockIdx.x * 16 + w * 4;
    float acc[16][4];
#pragma unroll
    for (int b = 0; b < 16; b++) { acc[b][0]=0;acc[b][1]=0;acc[b][2]=0;acc[b][3]=0; }
    gemv_core(g_hn, w1, o, DD, lane, acc);
#pragma unroll
    for (int b = 0; b < 16; b++)
#pragma unroll
        for (int j = 0; j < 4; j++) {
            float v = warp_sum(acc[b][j]);
            if (lane == 0) g_ff1[(size_t)b * HIDDEN + o + j] = v / (1.0f + __expf(-v));
        }
}

__global__ __launch_bounds__(128, 4) void gemv_out_kernel(
    const float* __restrict__ w2, const float* __restrict__ w3,
    float* __restrict__ out) {
    int lane = threadIdx.x & 31, w = threadIdx.x >> 5;
    int o = blockIdx.x * 16 + w * 4;
    float acc[16][4];
#pragma unroll
    for (int b = 0; b < 16; b++) { acc[b][0]=0;acc[b][1]=0;acc[b][2]=0;acc[b][3]=0; }
    gemv_core(g_ff1, w2, o, HIDDEN, lane, acc);
    gemv_core(g_hn,  w3, o, DD,     lane, acc);
#pragma unroll
    for (int b = 0; b < 16; b++)
#pragma unroll
        for (int j = 0; j < 4; j++) {
            float v = warp_sum(acc[b][j]);
            if (lane == 0) out[(size_t)b * DD + o + j] = g_h[(size_t)b * DD + o + j] + v;
        }
}

// ---------------- launch ----------------
extern "C" void kernel_launch(void* const* d_in, const int* in_sizes, int n_in,
                              void* d_out, int out_size) {
    const float* x         = (const float*)d_in[0];
    const float* freqs_cos = (const float*)d_in[1];
    const float* freqs_sin = (const float*)d_in[2];
    const float* cache_k   = (const float*)d_in[3];
    const float* cache_v   = (const float*)d_in[4];
    const float* wq_w      = (const float*)d_in[5];
    const float* wk_w      = (const float*)d_in[6];
    const float* wv_w      = (const float*)d_in[7];
    const float* wo_w      = (const float*)d_in[8];
    const float* w1_w      = (const float*)d_in[9];
    const float* w2_w      = (const float*)d_in[10];
    const float* w3_w      = (const float*)d_in[11];
    const float* attn_nw   = (const float*)d_in[12];
    const float* ffn_nw    = (const float*)d_in[13];
    float* out = (float*)d_out;

    // 1. xn = rmsnorm(x)
    rmsnorm_x_kernel<<<BB, 256>>>(x, attn_nw);
    // 2. q/k/v = xn @ {wq,wk,wv}.T
    gemv_qkv_kernel<<<192, 128>>>(wq_w, wk_w, wv_w);
    // 3. RoPE on q, k, v
    rope_kernel<<<(BB * 48 * 32 + 255) / 256, 256>>>(freqs_cos, freqs_sin);
    // 4. attention (T=4096; last position from g_k/g_v)
    attn_kernel<<<BB * NKV, 256>>>(cache_k, cache_v);
    // 5. h = x + attn @ wo.T
    gemv_wo_kernel<<<128, 128>>>(wo_w, x);
    // 6. hn = rmsnorm(h)
    rmsnorm_h_kernel<<<BB, 256>>>(ffn_nw);
    // 7. ff1 = silu(hn @ w1.T)
    gemv_w1_kernel<<<HIDDEN / 16, 128>>>(w1_w);
    // 8. out = h + ff1 @ w2.T + hn @ w3.T
    gemv_out_kernel<<<128, 128>>>(w2_w, w3_w, out);
}

// round 5
// speedup vs baseline: 1.3948x; 1.3948x over previous
#include <cuda_runtime.h>
#include <math.h>
#include <stdint.h>

#define BB 16
#define DD 2048
#define NH 32
#define NKV 8
#define HDIM 64
#define GRP 4
#define TSEQ 4096
#define HIDDEN 5632
#define KVD 512   // NKV*HDIM
#define NSPLIT 16
#define TCHUNK 256   // TSEQ / NSPLIT

// ---------------- scratch (device globals; no allocation allowed) ----------------
__device__ float g_xn[BB * DD];
__device__ float g_q[BB * DD];
__device__ float g_k[BB * KVD];
__device__ float g_v[BB * KVD];
__device__ float g_attn[BB * DD];
__device__ float g_h[BB * DD];
__device__ float g_hn[BB * DD];
__device__ float g_ff1[BB * HIDDEN];
// attention split partials
__device__ float g_po[BB * NKV * NSPLIT * GRP * HDIM];  // [pair*16+split][g][d]
__device__ float g_pm[BB * NKV * NSPLIT * GRP];
__device__ float g_pl[BB * NKV * NSPLIT * GRP];
// w2 K-split partials [ks][b][o]
__device__ float g_w2part[4][BB][DD];

// ---------------- helpers ----------------
__device__ __forceinline__ float warp_sum(float v) {
    v += __shfl_down_sync(0xffffffffu, v, 16);
    v += __shfl_down_sync(0xffffffffu, v, 8);
    v += __shfl_down_sync(0xffffffffu, v, 4);
    v += __shfl_down_sync(0xffffffffu, v, 2);
    v += __shfl_down_sync(0xffffffffu, v, 1);
    return v;
}

// acc[b][r] += dot(A[b, 4*c0+..], W[o0+r, ...]) over c in [c0,c1) float4 chunks
template <int R>
__device__ __forceinline__ void gemv_acc(const float* __restrict__ A,
                                         const float* __restrict__ W,
                                         int o0, int K, int c0, int c1,
                                         int lane, float acc[16][R]) {
#pragma unroll 4
    for (int c = c0 + lane; c < c1; c += 32) {
        float4 wv[R];
#pragma unroll
        for (int r = 0; r < R; r++)
            wv[r] = ((const float4*)(W + (size_t)(o0 + r) * K))[c];
#pragma unroll
        for (int b = 0; b < 16; b++) {
            float4 xv = ((const float4*)(A + (size_t)b * K))[c];
#pragma unroll
            for (int r = 0; r < R; r++)
                acc[b][r] += wv[r].x * xv.x + wv[r].y * xv.y +
                             wv[r].z * xv.z + wv[r].w * xv.w;
        }
    }
}

// ---------------- rmsnorm ----------------
__global__ void rmsnorm_x_kernel(const float* __restrict__ x,
                                 const float* __restrict__ w) {
    int b = blockIdx.x;
    const float* xr = x + (size_t)b * DD;
    float s = 0.f;
    for (int i = threadIdx.x; i < DD; i += 256) { float v = xr[i]; s += v * v; }
    for (int off = 16; off; off >>= 1) s += __shfl_xor_sync(0xffffffffu, s, off);
    __shared__ float red[8];
    int lane = threadIdx.x & 31, wid = threadIdx.x >> 5;
    if (lane == 0) red[wid] = s;
    __syncthreads();
    if (threadIdx.x == 0) {
        float t = 0.f;
#pragma unroll
        for (int i = 0; i < 8; i++) t += red[i];
        red[0] = rsqrtf(t * (1.0f / DD) + 1e-6f);
    }
    __syncthreads();
    float inv = red[0];
    float* orow = g_xn + (size_t)b * DD;
    for (int i = threadIdx.x; i < DD; i += 256) orow[i] = xr[i] * inv * w[i];
}

__global__ void rmsnorm_h_kernel(const float* __restrict__ w) {
    int b = blockIdx.x;
    const float* xr = g_h + (size_t)b * DD;
    float s = 0.f;
    for (int i = threadIdx.x; i < DD; i += 256) { float v = xr[i]; s += v * v; }
    for (int off = 16; off; off >>= 1) s += __shfl_xor_sync(0xffffffffu, s, off);
    __shared__ float red[8];
    int lane = threadIdx.x & 31, wid = threadIdx.x >> 5;
    if (lane == 0) red[wid] = s;
    __syncthreads();
    if (threadIdx.x == 0) {
        float t = 0.f;
#pragma unroll
        for (int i = 0; i < 8; i++) t += red[i];
        red[0] = rsqrtf(t * (1.0f / DD) + 1e-6f);
    }
    __syncthreads();
    float inv = red[0];
    float* orow = g_hn + (size_t)b * DD;
    for (int i = threadIdx.x; i < DD; i += 256) orow[i] = xr[i] * inv * w[i];
}

// ---------------- qkv: 8 rows/block (4 warps x 2 rows), grid 320 ----------------
__global__ __launch_bounds__(128) void gemv_qkv_kernel(
    const float* __restrict__ wq, const float* __restrict__ wk,
    const float* __restrict__ wv) {
    int lane = threadIdx.x & 31, w = threadIdx.x >> 5;
    int o = blockIdx.x * 8 + w * 2;
    const float* W; float* C; int oo, cst;
    if (o < 2048)      { W = wq; C = g_q; oo = o;        cst = DD;  }
    else if (o < 2560) { W = wk; C = g_k; oo = o - 2048; cst = KVD; }
    else               { W = wv; C = g_v; oo = o - 2560; cst = KVD; }
    float acc[16][2];
#pragma unroll
    for (int b = 0; b < 16; b++) { acc[b][0] = 0.f; acc[b][1] = 0.f; }
    gemv_acc<2>(g_xn, W, oo, DD, 0, DD / 4, lane, acc);
#pragma unroll
    for (int b = 0; b < 16; b++)
#pragma unroll
        for (int j = 0; j < 2; j++) {
            float v = warp_sum(acc[b][j]);
            if (lane == 0) C[(size_t)b * cst + oo + j] = v;
        }
}

// ---------------- rope ----------------
__global__ void rope_kernel(const float* __restrict__ cosv,
                            const float* __restrict__ sinv) {
    int idx = blockIdx.x * 256 + threadIdx.x;
    if (idx >= BB * 48 * 32) return;
    int b = idx / (48 * 32);
    int r = idx % (48 * 32);
    int head = r >> 5;
    int i = r & 31;
    float c = cosv[i], s = sinv[i];
    float* ptr;
    if (head < 32)      ptr = g_q + (size_t)b * DD  + head * 64;
    else if (head < 40) ptr = g_k + (size_t)b * KVD + (head - 32) * 64;
    else                ptr = g_v + (size_t)b * KVD + (head - 40) * 64;
    float x0 = ptr[2 * i], x1 = ptr[2 * i + 1];
    ptr[2 * i]     = x0 * c - x1 * s;
    ptr[2 * i + 1] = x0 * s + x1 * c;
}

// ---------------- attention: split-T flash, 2048 blocks ----------------
__global__ __launch_bounds__(256) void attn_split_kernel(
    const float* __restrict__ cache_k, const float* __restrict__ cache_v) {
    int blk = blockIdx.x;
    int pair = blk >> 4, split = blk & 15;
    int b = pair >> 3, kv = pair & 7;
    int t0 = split * TCHUNK;
    int tid = threadIdx.x, lane = tid & 31, wid = tid >> 5;

    __shared__ float q_s[4][64];
    __shared__ float s_s[4][TCHUNK];
    __shared__ float red[4][8];
    __shared__ float m_sh[4], l_sh[4];

    { // load + scale q
        int g = tid >> 6, d = tid & 63;
        q_s[g][d] = g_q[(size_t)b * DD + (kv * 4 + g) * 64 + d] * 0.125f;
    }
    __syncthreads();

    int c = lane & 3, p = lane >> 2;
    float qr[4][16];
#pragma unroll
    for (int g = 0; g < 4; g++)
#pragma unroll
        for (int j = 0; j < 16; j++) qr[g][j] = q_s[g][c * 16 + j];

    const float* kbase = cache_k + ((size_t)b * TSEQ * NKV + kv) * HDIM;
    const float* knew  = g_k + (size_t)(b * NKV + kv) * HDIM;

    // phase 1: scores -> smem
#pragma unroll
    for (int it = 0; it < 4; it++) {
        int tl = it * 64 + wid * 8 + p;
        int t = t0 + tl;
        const float* krow = (t < TSEQ - 1) ? (kbase + (size_t)t * KVD) : knew;
        const float4* k4 = (const float4*)(krow + c * 16);
        float4 k0 = k4[0], k1 = k4[1], k2 = k4[2], k3 = k4[3];
        float kv16[16] = {k0.x,k0.y,k0.z,k0.w, k1.x,k1.y,k1.z,k1.w,
                          k2.x,k2.y,k2.z,k2.w, k3.x,k3.y,k3.z,k3.w};
        float s[4];
#pragma unroll
        for (int g = 0; g < 4; g++) {
            float a = 0.f;
#pragma unroll
            for (int j = 0; j < 16; j++) a += qr[g][j] * kv16[j];
            s[g] = a;
        }
#pragma unroll
        for (int g = 0; g < 4; g++) {
            s[g] += __shfl_xor_sync(0xffffffffu, s[g], 1);
            s[g] += __shfl_xor_sync(0xffffffffu, s[g], 2);
        }
        if (c == 0) {
#pragma unroll
            for (int g = 0; g < 4; g++) s_s[g][tl] = s[g];
        }
    }
    __syncthreads();

    // phase 2: local softmax over TCHUNK (one element per thread per g)
    float lm[4];
#pragma unroll
    for (int g = 0; g < 4; g++) lm[g] = s_s[g][tid];
#pragma unroll
    for (int g = 0; g < 4; g++) {
        for (int off = 16; off; off >>= 1)
            lm[g] = fmaxf(lm[g], __shfl_xor_sync(0xffffffffu, lm[g], off));
        if (lane == 0) red[g][wid] = lm[g];
    }
    __syncthreads();
    if (tid < 4) {
        float m = -1e30f;
#pragma unroll
        for (int w = 0; w < 8; w++) m = fmaxf(m, red[tid][w]);
        m_sh[tid] = m;
    }
    __syncthreads();
    float ls[4];
#pragma unroll
    for (int g = 0; g < 4; g++) {
        float e = __expf(s_s[g][tid] - m_sh[g]);
        s_s[g][tid] = e;
        ls[g] = e;
    }
#pragma unroll
    for (int g = 0; g < 4; g++) {
        ls[g] = warp_sum(ls[g]);
        if (lane == 0) red[g][wid] = ls[g];
    }
    __syncthreads();
    if (tid < 4) {
        float s = 0.f;
#pragma unroll
        for (int w = 0; w < 8; w++) s += red[tid][w];
        l_sh[tid] = s;
        g_pm[blk * 4 + tid] = m_sh[tid];
        g_pl[blk * 4 + tid] = s;
    }
    __syncthreads();

    // phase 3: PV (unnormalized)
    int g = tid >> 6, d = tid & 63;
    const float* vbase = cache_v + ((size_t)b * TSEQ * NKV + kv) * HDIM + d;
    const float* pg = s_s[g];
    float a0 = 0.f, a1 = 0.f, a2 = 0.f, a3 = 0.f;
    int tmax = (split == NSPLIT - 1) ? (TCHUNK - 4) : TCHUNK;
    for (int tl = 0; tl < tmax; tl += 4) {
        int t = t0 + tl;
        a0 += pg[tl + 0] * vbase[(size_t)(t + 0) * KVD];
        a1 += pg[tl + 1] * vbase[(size_t)(t + 1) * KVD];
        a2 += pg[tl + 2] * vbase[(size_t)(t + 2) * KVD];
        a3 += pg[tl + 3] * vbase[(size_t)(t + 3) * KVD];
    }
    if (split == NSPLIT - 1) {
        int tl = TCHUNK - 4, t = t0 + tl;
        a0 += pg[tl + 0] * vbase[(size_t)(t + 0) * KVD];
        a1 += pg[tl + 1] * vbase[(size_t)(t + 1) * KVD];
        a2 += pg[tl + 2] * vbase[(size_t)(t + 2) * KVD];
        a3 += pg[tl + 3] * g_v[(size_t)(b * NKV + kv) * HDIM + d];
    }
    g_po[(size_t)blk * 256 + g * 64 + d] = a0 + a1 + a2 + a3;
}

// combine split partials: grid = 128 pairs
__global__ __launch_bounds__(256) void attn_reduce_kernel() {
    int pair = blockIdx.x;
    int b = pair >> 3, kv = pair & 7;
    int tid = threadIdx.x, g = tid >> 6, d = tid & 63;
    float m = -1e30f;
#pragma unroll
    for (int s = 0; s < NSPLIT; s++)
        m = fmaxf(m, g_pm[(pair * NSPLIT + s) * 4 + g]);
    float l = 0.f, o = 0.f;
#pragma unroll
    for (int s = 0; s < NSPLIT; s++) {
        int bs = pair * NSPLIT + s;
        float w = __expf(g_pm[bs * 4 + g] - m);
        l += g_pl[bs * 4 + g] * w;
        o += g_po[(size_t)bs * 256 + g * 64 + d] * w;
    }
    g_attn[(size_t)b * DD + (kv * 4 + g) * 64 + d] = o / l;
}

// ---------------- wo: 8 rows/block, grid 256, + residual ----------------
__global__ __launch_bounds__(128) void gemv_wo_kernel(
    const float* __restrict__ wo, const float* __restrict__ x) {
    int lane = threadIdx.x & 31, w = threadIdx.x >> 5;
    int o = blockIdx.x * 8 + w * 2;
    float acc[16][2];
#pragma unroll
    for (int b = 0; b < 16; b++) { acc[b][0] = 0.f; acc[b][1] = 0.f; }
    gemv_acc<2>(g_attn, wo, o, DD, 0, DD / 4, lane, acc);
#pragma unroll
    for (int b = 0; b < 16; b++)
#pragma unroll
        for (int j = 0; j < 2; j++) {
            float v = warp_sum(acc[b][j]);
            if (lane == 0)
                g_h[(size_t)b * DD + o + j] = v + x[(size_t)b * DD + o + j];
        }
}

// ---------------- w1 + silu: 16 rows/block, grid 352 ----------------
__global__ __launch_bounds__(128) void gemv_w1_kernel(const float* __restrict__ w1) {
    int lane = threadIdx.x & 31, w = threadIdx.x >> 5;
    int o = blockIdx.x * 16 + w * 4;
    float acc[16][4];
#pragma unroll
    for (int b = 0; b < 16; b++)
#pragma unroll
        for (int j = 0; j < 4; j++) acc[b][j] = 0.f;
    gemv_acc<4>(g_hn, w1, o, DD, 0, DD / 4, lane, acc);
#pragma unroll
    for (int b = 0; b < 16; b++)
#pragma unroll
        for (int j = 0; j < 4; j++) {
            float v = warp_sum(acc[b][j]);
            if (lane == 0)
                g_ff1[(size_t)b * HIDDEN + o + j] = v / (1.0f + __expf(-v));
        }
}

// ---------------- w2: 32 rows/block, K split x4 (1408 each), grid 256 ----------------
__global__ __launch_bounds__(128) void gemv_w2_kernel(const float* __restrict__ w2) {
    int lane = threadIdx.x & 31, w = threadIdx.x >> 5;
    int rg = blockIdx.x >> 2, ks = blockIdx.x & 3;
    int o = rg * 32 + w * 8;
    int c0 = ks * (HIDDEN / 16);       // 1408/4 = 352 float4s per split
    int c1 = c0 + (HIDDEN / 16);
    float acc[16][8];
#pragma unroll
    for (int b = 0; b < 16; b++)
#pragma unroll
        for (int j = 0; j < 8; j++) acc[b][j] = 0.f;
    gemv_acc<8>(g_ff1, w2, o, HIDDEN, c0, c1, lane, acc);
#pragma unroll
    for (int b = 0; b < 16; b++)
#pragma unroll
        for (int j = 0; j < 8; j++) {
            float v = warp_sum(acc[b][j]);
            if (lane == 0) g_w2part[ks][b][o + j] = v;
        }
}

// ---------------- w3 + finalize: 8 rows/block, grid 256 ----------------
__global__ __launch_bounds__(128) void gemv_w3fin_kernel(
    const float* __restrict__ w3, float* __restrict__ out) {
    int lane = threadIdx.x & 31, w = threadIdx.x >> 5;
    int o = blockIdx.x * 8 + w * 2;
    float acc[16][2];
#pragma unroll
    for (int b = 0; b < 16; b++) { acc[b][0] = 0.f; acc[b][1] = 0.f; }
    gemv_acc<2>(g_hn, w3, o, DD, 0, DD / 4, lane, acc);
#pragma unroll
    for (int b = 0; b < 16; b++)
#pragma unroll
        for (int j = 0; j < 2; j++) {
            float v = warp_sum(acc[b][j]);
            if (lane == 0) {
                int oj = o + j;
                float r = g_h[(size_t)b * DD + oj] + v
                        + g_w2part[0][b][oj] + g_w2part[1][b][oj]
                        + g_w2part[2][b][oj] + g_w2part[3][b][oj];
                out[(size_t)b * DD + oj] = r;
            }
        }
}

// ---------------- launch ----------------
extern "C" void kernel_launch(void* const* d_in, const int* in_sizes, int n_in,
                              void* d_out, int out_size) {
    const float* x         = (const float*)d_in[0];
    const float* freqs_cos = (const float*)d_in[1];
    const float* freqs_sin = (const float*)d_in[2];
    const float* cache_k   = (const float*)d_in[3];
    const float* cache_v   = (const float*)d_in[4];
    const float* wq_w      = (const float*)d_in[5];
    const float* wk_w      = (const float*)d_in[6];
    const float* wv_w      = (const float*)d_in[7];
    const float* wo_w      = (const float*)d_in[8];
    const float* w1_w      = (const float*)d_in[9];
    const float* w2_w      = (const float*)d_in[10];
    const float* w3_w      = (const float*)d_in[11];
    const float* attn_nw   = (const float*)d_in[12];
    const float* ffn_nw    = (const float*)d_in[13];
    float* out = (float*)d_out;

    rmsnorm_x_kernel<<<BB, 256>>>(x, attn_nw);
    gemv_qkv_kernel<<<3072 / 8, 128>>>(wq_w, wk_w, wv_w);
    rope_kernel<<<(BB * 48 * 32 + 255) / 256, 256>>>(freqs_cos, freqs_sin);
    attn_split_kernel<<<BB * NKV * NSPLIT, 256>>>(cache_k, cache_v);
    attn_reduce_kernel<<<BB * NKV, 256>>>();
    gemv_wo_kernel<<<DD / 8, 128>>>(wo_w, x);
    rmsnorm_h_kernel<<<BB, 256>>>(ffn_nw);
    gemv_w1_kernel<<<HIDDEN / 16, 128>>>(w1_w);
    gemv_w2_kernel<<<(DD / 32) * 4, 128>>>(w2_w);
    gemv_w3fin_kernel<<<DD / 8, 128>>>(w3_w, out);
}

// round 6
// speedup vs baseline: 1.8530x; 1.3285x over previous
#include <cuda_runtime.h>
#include <math.h>
#include <stdint.h>

#define BB 16
#define DD 2048
#define NH 32
#define NKV 8
#define HDIM 64
#define GRP 4
#define TSEQ 4096
#define HIDDEN 5632
#define KVD 512
#define NSPLIT 16
#define TCHUNK 256

// ---------------- scratch ----------------
__device__ float g_xn[BB * DD];
__device__ float g_q[BB * DD];
__device__ float g_k[BB * KVD];
__device__ float g_v[BB * KVD];
__device__ float g_attn[BB * DD];
__device__ float g_h[BB * DD];
__device__ float g_hn[BB * DD];
__device__ float g_ff1[BB * HIDDEN];
__device__ float g_ff2[BB * DD];
__device__ float g_po[BB * NKV * NSPLIT * GRP * HDIM];
__device__ float g_pm[BB * NKV * NSPLIT * GRP];
__device__ float g_pl[BB * NKV * NSPLIT * GRP];

__device__ __forceinline__ float warp_sum(float v) {
    v += __shfl_down_sync(0xffffffffu, v, 16);
    v += __shfl_down_sync(0xffffffffu, v, 8);
    v += __shfl_down_sync(0xffffffffu, v, 4);
    v += __shfl_down_sync(0xffffffffu, v, 2);
    v += __shfl_down_sync(0xffffffffu, v, 1);
    return v;
}

// ---------------- GEMV core: 256 thr, warps 0-3 lower K half, 4-7 upper ----------------
template <int R>
__device__ __forceinline__ void gemv_warp_part(const float* __restrict__ A,
                                               const float* __restrict__ W,
                                               int o0, int K, int c0, int c1,
                                               int lane, float acc[16][R]) {
#pragma unroll 2
    for (int c = c0 + lane; c < c1; c += 32) {
        float4 wv[R];
#pragma unroll
        for (int r = 0; r < R; r++)
            wv[r] = __ldcs(((const float4*)(W + (size_t)(o0 + r) * K)) + c);
#pragma unroll
        for (int b = 0; b < 16; b++) {
            float4 xv = ((const float4*)(A + (size_t)b * K))[c];
#pragma unroll
            for (int r = 0; r < R; r++)
                acc[b][r] += wv[r].x * xv.x + wv[r].y * xv.y +
                             wv[r].z * xv.z + wv[r].w * xv.w;
        }
    }
}

// Computes rows [row0, row0+4R) of A @ W.T for 16 batches. Valid for tid < 64R:
// returns true with *pb = batch, *prr = row offset within block, *pv = value.
template <int R>
__device__ __forceinline__ bool gemv_block_core(const float* __restrict__ A,
                                                const float* __restrict__ W,
                                                int K, int row0, int tid,
                                                int* pb, int* prr, float* pv) {
    __shared__ float s_part[8][16][R];
    int lane = tid & 31, w = tid >> 5;
    int rg = w & 3, half = w >> 2;
    int o0 = row0 + rg * R;
    int KH = K / 8;   // float4 chunks per half
    float acc[16][R];
#pragma unroll
    for (int b = 0; b < 16; b++)
#pragma unroll
        for (int r = 0; r < R; r++) acc[b][r] = 0.f;
    gemv_warp_part<R>(A, W, o0, K, half * KH, (half + 1) * KH, lane, acc);
#pragma unroll
    for (int b = 0; b < 16; b++)
#pragma unroll
        for (int r = 0; r < R; r++) {
            float v = warp_sum(acc[b][r]);
            if (lane == 0) s_part[w][b][r] = v;
        }
    __syncthreads();
    if (tid < 64 * R) {
        int b = tid / (4 * R), rr = tid % (4 * R);
        int rg2 = rr / R, r2 = rr % R;
        *pb = b; *prr = rr;
        *pv = s_part[rg2][b][r2] + s_part[rg2 + 4][b][r2];
        return true;
    }
    return false;
}

// ---------------- rmsnorm ----------------
__global__ void rmsnorm_x_kernel(const float* __restrict__ x,
                                 const float* __restrict__ w) {
    int b = blockIdx.x;
    const float* xr = x + (size_t)b * DD;
    float s = 0.f;
    for (int i = threadIdx.x; i < DD; i += 256) { float v = xr[i]; s += v * v; }
    for (int off = 16; off; off >>= 1) s += __shfl_xor_sync(0xffffffffu, s, off);
    __shared__ float red[8];
    int lane = threadIdx.x & 31, wid = threadIdx.x >> 5;
    if (lane == 0) red[wid] = s;
    __syncthreads();
    if (threadIdx.x == 0) {
        float t = 0.f;
#pragma unroll
        for (int i = 0; i < 8; i++) t += red[i];
        red[0] = rsqrtf(t * (1.0f / DD) + 1e-6f);
    }
    __syncthreads();
    float inv = red[0];
    float* orow = g_xn + (size_t)b * DD;
    for (int i = threadIdx.x; i < DD; i += 256) orow[i] = xr[i] * inv * w[i];
}

__global__ void rmsnorm_h_kernel(const float* __restrict__ w) {
    int b = blockIdx.x;
    const float* xr = g_h + (size_t)b * DD;
    float s = 0.f;
    for (int i = threadIdx.x; i < DD; i += 256) { float v = xr[i]; s += v * v; }
    for (int off = 16; off; off >>= 1) s += __shfl_xor_sync(0xffffffffu, s, off);
    __shared__ float red[8];
    int lane = threadIdx.x & 31, wid = threadIdx.x >> 5;
    if (lane == 0) red[wid] = s;
    __syncthreads();
    if (threadIdx.x == 0) {
        float t = 0.f;
#pragma unroll
        for (int i = 0; i < 8; i++) t += red[i];
        red[0] = rsqrtf(t * (1.0f / DD) + 1e-6f);
    }
    __syncthreads();
    float inv = red[0];
    float* orow = g_hn + (size_t)b * DD;
    for (int i = threadIdx.x; i < DD; i += 256) orow[i] = xr[i] * inv * w[i];
}

// ---------------- GEMV kernels ----------------
__global__ __launch_bounds__(256) void gemv_qkv_kernel(
    const float* __restrict__ wq, const float* __restrict__ wk,
    const float* __restrict__ wv) {
    int row0 = blockIdx.x * 8;
    const float* Wm; int wrow0;
    if (row0 < 2048)      { Wm = wq; wrow0 = row0; }
    else if (row0 < 2560) { Wm = wk; wrow0 = row0 - 2048; }
    else                  { Wm = wv; wrow0 = row0 - 2560; }
    int b, rr; float v;
    if (gemv_block_core<2>(g_xn, Wm, DD, wrow0, threadIdx.x, &b, &rr, &v)) {
        int row = wrow0 + rr;
        if (row0 < 2048)      g_q[(size_t)b * DD + row] = v;
        else if (row0 < 2560) g_k[(size_t)b * KVD + row] = v;
        else                  g_v[(size_t)b * KVD + row] = v;
    }
}

__global__ __launch_bounds__(256) void gemv_wo_kernel(
    const float* __restrict__ wo, const float* __restrict__ x) {
    int row0 = blockIdx.x * 8;
    int b, rr; float v;
    if (gemv_block_core<2>(g_attn, wo, DD, row0, threadIdx.x, &b, &rr, &v)) {
        int row = row0 + rr;
        g_h[(size_t)b * DD + row] = v + x[(size_t)b * DD + row];
    }
}

__global__ __launch_bounds__(256) void gemv_w1_kernel(const float* __restrict__ w1) {
    int row0 = blockIdx.x * 16;
    int b, rr; float v;
    if (gemv_block_core<4>(g_hn, w1, DD, row0, threadIdx.x, &b, &rr, &v)) {
        int row = row0 + rr;
        g_ff1[(size_t)b * HIDDEN + row] = v / (1.0f + __expf(-v));
    }
}

__global__ __launch_bounds__(256) void gemv_w2_kernel(const float* __restrict__ w2) {
    int row0 = blockIdx.x * 8;
    int b, rr; float v;
    if (gemv_block_core<2>(g_ff1, w2, HIDDEN, row0, threadIdx.x, &b, &rr, &v)) {
        int row = row0 + rr;
        g_ff2[(size_t)b * DD + row] = v;
    }
}

__global__ __launch_bounds__(256) void gemv_w3fin_kernel(
    const float* __restrict__ w3, float* __restrict__ out) {
    int row0 = blockIdx.x * 8;
    int b, rr; float v;
    if (gemv_block_core<2>(g_hn, w3, DD, row0, threadIdx.x, &b, &rr, &v)) {
        int row = row0 + rr;
        out[(size_t)b * DD + row] =
            g_h[(size_t)b * DD + row] + g_ff2[(size_t)b * DD + row] + v;
    }
}

// ---------------- rope ----------------
__global__ void rope_kernel(const float* __restrict__ cosv,
                            const float* __restrict__ sinv) {
    int idx = blockIdx.x * 256 + threadIdx.x;
    if (idx >= BB * 48 * 32) return;
    int b = idx / (48 * 32);
    int r = idx % (48 * 32);
    int head = r >> 5;
    int i = r & 31;
    float c = cosv[i], s = sinv[i];
    float* ptr;
    if (head < 32)      ptr = g_q + (size_t)b * DD  + head * 64;
    else if (head < 40) ptr = g_k + (size_t)b * KVD + (head - 32) * 64;
    else                ptr = g_v + (size_t)b * KVD + (head - 40) * 64;
    float x0 = ptr[2 * i], x1 = ptr[2 * i + 1];
    ptr[2 * i]     = x0 * c - x1 * s;
    ptr[2 * i + 1] = x0 * s + x1 * c;
}

// ---------------- attention split kernel ----------------
__global__ __launch_bounds__(256) void attn_split_kernel(
    const float* __restrict__ cache_k, const float* __restrict__ cache_v) {
    int blk = blockIdx.x;
    int pair = blk >> 4, split = blk & 15;
    int b = pair >> 3, kv = pair & 7;
    int t0 = split * TCHUNK;
    int tid = threadIdx.x, lane = tid & 31, wid = tid >> 5;

    __shared__ float q_s[4][64];
    __shared__ float4 s_sT[TCHUNK];          // [t] -> (g0,g1,g2,g3)
    __shared__ float red[4][8];
    __shared__ float m_sh[4];
    __shared__ float o_part[4][4][64];       // [quarter][g][d]

    { // load + scale q
        int g = tid >> 6, d = tid & 63;
        q_s[g][d] = g_q[(size_t)b * DD + (kv * 4 + g) * 64 + d] * 0.125f;
    }
    __syncthreads();

    int c = lane & 7, p = lane >> 3;
    float qr[4][8];
#pragma unroll
    for (int g = 0; g < 4; g++)
#pragma unroll
        for (int j = 0; j < 8; j++) qr[g][j] = q_s[g][c * 8 + j];

    const float* kbase = cache_k + ((size_t)b * TSEQ * NKV + kv) * HDIM;
    const float* knew  = g_k + (size_t)(b * NKV + kv) * HDIM;

    // phase 1: scores -> smem [t][g]
#pragma unroll 2
    for (int it = 0; it < 8; it++) {
        int tl = it * 32 + wid * 4 + p;
        int t = t0 + tl;
        const float* krow = (t < TSEQ - 1) ? (kbase + (size_t)t * KVD) : knew;
        const float4* k4 = (const float4*)krow;
        float4 k0 = __ldcs(k4 + c * 2);
        float4 k1 = __ldcs(k4 + c * 2 + 1);
        float kv8[8] = {k0.x, k0.y, k0.z, k0.w, k1.x, k1.y, k1.z, k1.w};
        float4 s;
        {
            float a0 = 0.f, a1 = 0.f, a2 = 0.f, a3 = 0.f;
#pragma unroll
            for (int j = 0; j < 8; j++) {
                a0 += qr[0][j] * kv8[j];
                a1 += qr[1][j] * kv8[j];
                a2 += qr[2][j] * kv8[j];
                a3 += qr[3][j] * kv8[j];
            }
            s.x = a0; s.y = a1; s.z = a2; s.w = a3;
        }
#pragma unroll
        for (int off = 1; off <= 4; off <<= 1) {
            s.x += __shfl_xor_sync(0xffffffffu, s.x, off);
            s.y += __shfl_xor_sync(0xffffffffu, s.y, off);
            s.z += __shfl_xor_sync(0xffffffffu, s.z, off);
            s.w += __shfl_xor_sync(0xffffffffu, s.w, off);
        }
        if (c == 0) s_sT[tl] = s;
    }
    __syncthreads();

    // phase 2: local softmax
    float4 sv = s_sT[tid];
    float lm[4] = {sv.x, sv.y, sv.z, sv.w};
#pragma unroll
    for (int g = 0; g < 4; g++) {
        for (int off = 16; off; off >>= 1)
            lm[g] = fmaxf(lm[g], __shfl_xor_sync(0xffffffffu, lm[g], off));
        if (lane == 0) red[g][wid] = lm[g];
    }
    __syncthreads();
    if (tid < 4) {
        float m = -1e30f;
#pragma unroll
        for (int w = 0; w < 8; w++) m = fmaxf(m, red[tid][w]);
        m_sh[tid] = m;
    }
    __syncthreads();
    float4 ev;
    ev.x = __expf(sv.x - m_sh[0]);
    ev.y = __expf(sv.y - m_sh[1]);
    ev.z = __expf(sv.z - m_sh[2]);
    ev.w = __expf(sv.w - m_sh[3]);
    s_sT[tid] = ev;
    float ls[4] = {ev.x, ev.y, ev.z, ev.w};
#pragma unroll
    for (int g = 0; g < 4; g++) {
        ls[g] = warp_sum(ls[g]);
        if (lane == 0) red[g][wid] = ls[g];
    }
    __syncthreads();
    if (tid < 4) {
        float s = 0.f;
#pragma unroll
        for (int w = 0; w < 8; w++) s += red[tid][w];
        g_pm[blk * 4 + tid] = m_sh[tid];
        g_pl[blk * 4 + tid] = s;
    }
    __syncthreads();

    // phase 3: PV — thread (quarter, d); each V element read once per CTA
    {
        int qq = tid >> 6, d = tid & 63;
        const float* vcol = cache_v + ((size_t)b * TSEQ * NKV + kv) * HDIM + d;
        const float* vnew = g_v + (size_t)(b * NKV + kv) * HDIM + d;
        float o0 = 0.f, o1 = 0.f, o2 = 0.f, o3 = 0.f;
        int tlb = qq * 64;
#pragma unroll 4
        for (int i = 0; i < 64; i++) {
            int tl = tlb + i;
            int t = t0 + tl;
            float v = (t < TSEQ - 1) ? __ldcs(vcol + (size_t)t * KVD) : *vnew;
            float4 pv = s_sT[tl];
            o0 += pv.x * v; o1 += pv.y * v; o2 += pv.z * v; o3 += pv.w * v;
        }
        o_part[qq][0][d] = o0;
        o_part[qq][1][d] = o1;
        o_part[qq][2][d] = o2;
        o_part[qq][3][d] = o3;
    }
    __syncthreads();
    {
        int g = tid >> 6, d = tid & 63;
        float sum = o_part[0][g][d] + o_part[1][g][d] +
                    o_part[2][g][d] + o_part[3][g][d];
        g_po[(size_t)blk * 256 + g * 64 + d] = sum;
    }
}

// combine split partials
__global__ __launch_bounds__(256) void attn_reduce_kernel() {
    int pair = blockIdx.x;
    int b = pair >> 3, kv = pair & 7;
    int tid = threadIdx.x, g = tid >> 6, d = tid & 63;
    float m = -1e30f;
#pragma unroll
    for (int s = 0; s < NSPLIT; s++)
        m = fmaxf(m, g_pm[(pair * NSPLIT + s) * 4 + g]);
    float l = 0.f, o = 0.f;
#pragma unroll
    for (int s = 0; s < NSPLIT; s++) {
        int bs = pair * NSPLIT + s;
        float w = __expf(g_pm[bs * 4 + g] - m);
        l += g_pl[bs * 4 + g] * w;
        o += g_po[(size_t)bs * 256 + g * 64 + d] * w;
    }
    g_attn[(size_t)b * DD + (kv * 4 + g) * 64 + d] = o / l;
}

// ---------------- launch ----------------
extern "C" void kernel_launch(void* const* d_in, const int* in_sizes, int n_in,
                              void* d_out, int out_size) {
    const float* x         = (const float*)d_in[0];
    const float* freqs_cos = (const float*)d_in[1];
    const float* freqs_sin = (const float*)d_in[2];
    const float* cache_k   = (const float*)d_in[3];
    const float* cache_v   = (const float*)d_in[4];
    const float* wq_w      = (const float*)d_in[5];
    const float* wk_w      = (const float*)d_in[6];
    const float* wv_w      = (const float*)d_in[7];
    const float* wo_w      = (const float*)d_in[8];
    const float* w1_w      = (const float*)d_in[9];
    const float* w2_w      = (const float*)d_in[10];
    const float* w3_w      = (const float*)d_in[11];
    const float* attn_nw   = (const float*)d_in[12];
    const float* ffn_nw    = (const float*)d_in[13];
    float* out = (float*)d_out;

    rmsnorm_x_kernel<<<BB, 256>>>(x, attn_nw);
    gemv_qkv_kernel<<<3072 / 8, 256>>>(wq_w, wk_w, wv_w);
    rope_kernel<<<(BB * 48 * 32 + 255) / 256, 256>>>(freqs_cos, freqs_sin);
    attn_split_kernel<<<BB * NKV * NSPLIT, 256>>>(cache_k, cache_v);
    attn_reduce_kernel<<<BB * NKV, 256>>>();
    gemv_wo_kernel<<<DD / 8, 256>>>(wo_w, x);
    rmsnorm_h_kernel<<<BB, 256>>>(ffn_nw);
    gemv_w1_kernel<<<HIDDEN / 16, 256>>>(w1_w);
    gemv_w2_kernel<<<DD / 8, 256>>>(w2_w);
    gemv_w3fin_kernel<<<DD / 8, 256>>>(w3_w, out);
}

// round 7
// speedup vs baseline: 2.1133x; 1.1404x over previous
#include <cuda_runtime.h>
#include <math.h>
#include <stdint.h>

#define BB 16
#define DD 2048
#define NH 32
#define NKV 8
#define HDIM 64
#define GRP 4
#define TSEQ 4096
#define HIDDEN 5632
#define KVD 512
#define NSPLIT 32
#define TCHUNK 128

// ---------------- scratch ----------------
__device__ float g_xn[BB * DD];
__device__ float g_q[BB * DD];
__device__ float g_k[BB * KVD];
__device__ float g_v[BB * KVD];
__device__ float g_attn[BB * DD];
__device__ float g_h[BB * DD];
__device__ float g_hn[BB * DD];
__device__ float g_ff1[BB * HIDDEN];
__device__ float g_ff2[BB * DD];
__device__ float g_po[BB * NKV * NSPLIT * GRP * HDIM];   // 4 MB
__device__ float g_pl[BB * NKV * NSPLIT * GRP];

__device__ __forceinline__ float warp_sum(float v) {
    v += __shfl_down_sync(0xffffffffu, v, 16);
    v += __shfl_down_sync(0xffffffffu, v, 8);
    v += __shfl_down_sync(0xffffffffu, v, 4);
    v += __shfl_down_sync(0xffffffffu, v, 2);
    v += __shfl_down_sync(0xffffffffu, v, 1);
    return v;
}

// ---------------- GEMV warp core: weight prefetch depth 4 ----------------
template <int R>
__device__ __forceinline__ void gemv_warp_part(const float* __restrict__ A,
                                               const float* __restrict__ W,
                                               int o0, int K, int c0, int c1,
                                               int lane, float acc[16][R]) {
    int c = c0 + lane;
    // main: 4 c-chunks in flight (front-batched __ldcs weight loads)
    for (; c + 96 < c1; c += 128) {
        float4 wv[4][R];
#pragma unroll
        for (int u = 0; u < 4; u++)
#pragma unroll
            for (int r = 0; r < R; r++)
                wv[u][r] = __ldcs(((const float4*)(W + (size_t)(o0 + r) * K)) + c + u * 32);
#pragma unroll
        for (int u = 0; u < 4; u++)
#pragma unroll
            for (int b = 0; b < 16; b++) {
                float4 xv = ((const float4*)(A + (size_t)b * K))[c + u * 32];
#pragma unroll
                for (int r = 0; r < R; r++)
                    acc[b][r] += wv[u][r].x * xv.x + wv[u][r].y * xv.y +
                                 wv[u][r].z * xv.z + wv[u][r].w * xv.w;
            }
    }
    // tail
    for (; c < c1; c += 32) {
        float4 wv[R];
#pragma unroll
        for (int r = 0; r < R; r++)
            wv[r] = __ldcs(((const float4*)(W + (size_t)(o0 + r) * K)) + c);
#pragma unroll
        for (int b = 0; b < 16; b++) {
            float4 xv = ((const float4*)(A + (size_t)b * K))[c];
#pragma unroll
            for (int r = 0; r < R; r++)
                acc[b][r] += wv[r].x * xv.x + wv[r].y * xv.y +
                             wv[r].z * xv.z + wv[r].w * xv.w;
        }
    }
}

// 256 thr: warp w -> row-group (w&3), K-half (w>>2). Rows/block = 4R.
template <int R>
__device__ __forceinline__ bool gemv_block_core(const float* __restrict__ A,
                                                const float* __restrict__ W,
                                                int K, int row0, int tid,
                                                int* pb, int* prr, float* pv) {
    __shared__ float s_part[8][16][R];
    int lane = tid & 31, w = tid >> 5;
    int rg = w & 3, half = w >> 2;
    int o0 = row0 + rg * R;
    int KH = K / 8;   // float4 chunks per half
    float acc[16][R];
#pragma unroll
    for (int b = 0; b < 16; b++)
#pragma unroll
        for (int r = 0; r < R; r++) acc[b][r] = 0.f;
    gemv_warp_part<R>(A, W, o0, K, half * KH, (half + 1) * KH, lane, acc);
#pragma unroll
    for (int b = 0; b < 16; b++)
#pragma unroll
        for (int r = 0; r < R; r++) {
            float v = warp_sum(acc[b][r]);
            if (lane == 0) s_part[w][b][r] = v;
        }
    __syncthreads();
    if (tid < 64 * R) {
        int b = tid / (4 * R), rr = tid % (4 * R);
        int rg2 = rr / R, r2 = rr % R;
        *pb = b; *prr = rr;
        *pv = s_part[rg2][b][r2] + s_part[rg2 + 4][b][r2];
        return true;
    }
    return false;
}

// ---------------- rmsnorm ----------------
__global__ void rmsnorm_x_kernel(const float* __restrict__ x,
                                 const float* __restrict__ w) {
    int b = blockIdx.x;
    const float* xr = x + (size_t)b * DD;
    float s = 0.f;
    for (int i = threadIdx.x; i < DD; i += 256) { float v = xr[i]; s += v * v; }
    for (int off = 16; off; off >>= 1) s += __shfl_xor_sync(0xffffffffu, s, off);
    __shared__ float red[8];
    int lane = threadIdx.x & 31, wid = threadIdx.x >> 5;
    if (lane == 0) red[wid] = s;
    __syncthreads();
    if (threadIdx.x == 0) {
        float t = 0.f;
#pragma unroll
        for (int i = 0; i < 8; i++) t += red[i];
        red[0] = rsqrtf(t * (1.0f / DD) + 1e-6f);
    }
    __syncthreads();
    float inv = red[0];
    float* orow = g_xn + (size_t)b * DD;
    for (int i = threadIdx.x; i < DD; i += 256) orow[i] = xr[i] * inv * w[i];
}

__global__ void rmsnorm_h_kernel(const float* __restrict__ w) {
    int b = blockIdx.x;
    const float* xr = g_h + (size_t)b * DD;
    float s = 0.f;
    for (int i = threadIdx.x; i < DD; i += 256) { float v = xr[i]; s += v * v; }
    for (int off = 16; off; off >>= 1) s += __shfl_xor_sync(0xffffffffu, s, off);
    __shared__ float red[8];
    int lane = threadIdx.x & 31, wid = threadIdx.x >> 5;
    if (lane == 0) red[wid] = s;
    __syncthreads();
    if (threadIdx.x == 0) {
        float t = 0.f;
#pragma unroll
        for (int i = 0; i < 8; i++) t += red[i];
        red[0] = rsqrtf(t * (1.0f / DD) + 1e-6f);
    }
    __syncthreads();
    float inv = red[0];
    float* orow = g_hn + (size_t)b * DD;
    for (int i = threadIdx.x; i < DD; i += 256) orow[i] = xr[i] * inv * w[i];
}

// ---------------- GEMV kernels ----------------
__global__ __launch_bounds__(256) void gemv_qkv_kernel(
    const float* __restrict__ wq, const float* __restrict__ wk,
    const float* __restrict__ wv) {
    int row0 = blockIdx.x * 8;
    const float* Wm; int wrow0;
    if (row0 < 2048)      { Wm = wq; wrow0 = row0; }
    else if (row0 < 2560) { Wm = wk; wrow0 = row0 - 2048; }
    else                  { Wm = wv; wrow0 = row0 - 2560; }
    int b, rr; float v;
    if (gemv_block_core<2>(g_xn, Wm, DD, wrow0, threadIdx.x, &b, &rr, &v)) {
        int row = wrow0 + rr;
        if (row0 < 2048)      g_q[(size_t)b * DD + row] = v;
        else if (row0 < 2560) g_k[(size_t)b * KVD + row] = v;
        else                  g_v[(size_t)b * KVD + row] = v;
    }
}

__global__ __launch_bounds__(256) void gemv_wo_kernel(
    const float* __restrict__ wo, const float* __restrict__ x) {
    int row0 = blockIdx.x * 8;
    int b, rr; float v;
    if (gemv_block_core<2>(g_attn, wo, DD, row0, threadIdx.x, &b, &rr, &v)) {
        int row = row0 + rr;
        g_h[(size_t)b * DD + row] = v + x[(size_t)b * DD + row];
    }
}

__global__ __launch_bounds__(256) void gemv_w1_kernel(const float* __restrict__ w1) {
    int row0 = blockIdx.x * 8;
    int b, rr; float v;
    if (gemv_block_core<2>(g_hn, w1, DD, row0, threadIdx.x, &b, &rr, &v)) {
        int row = row0 + rr;
        g_ff1[(size_t)b * HIDDEN + row] = v / (1.0f + __expf(-v));
    }
}

__global__ __launch_bounds__(256) void gemv_w2_kernel(const float* __restrict__ w2) {
    int row0 = blockIdx.x * 8;
    int b, rr; float v;
    if (gemv_block_core<2>(g_ff1, w2, HIDDEN, row0, threadIdx.x, &b, &rr, &v)) {
        int row = row0 + rr;
        g_ff2[(size_t)b * DD + row] = v;
    }
}

__global__ __launch_bounds__(256) void gemv_w3fin_kernel(
    const float* __restrict__ w3, float* __restrict__ out) {
    int row0 = blockIdx.x * 8;
    int b, rr; float v;
    if (gemv_block_core<2>(g_hn, w3, DD, row0, threadIdx.x, &b, &rr, &v)) {
        int row = row0 + rr;
        out[(size_t)b * DD + row] =
            g_h[(size_t)b * DD + row] + g_ff2[(size_t)b * DD + row] + v;
    }
}

// ---------------- rope ----------------
__global__ void rope_kernel(const float* __restrict__ cosv,
                            const float* __restrict__ sinv) {
    int idx = blockIdx.x * 256 + threadIdx.x;
    if (idx >= BB * 48 * 32) return;
    int b = idx / (48 * 32);
    int r = idx % (48 * 32);
    int head = r >> 5;
    int i = r & 31;
    float c = cosv[i], s = sinv[i];
    float* ptr;
    if (head < 32)      ptr = g_q + (size_t)b * DD  + head * 64;
    else if (head < 40) ptr = g_k + (size_t)b * KVD + (head - 32) * 64;
    else                ptr = g_v + (size_t)b * KVD + (head - 40) * 64;
    float x0 = ptr[2 * i], x1 = ptr[2 * i + 1];
    ptr[2 * i]     = x0 * c - x1 * s;
    ptr[2 * i + 1] = x0 * s + x1 * c;
}

// ---------------- attention split kernel (no max-sub; scores bounded) ------
__global__ __launch_bounds__(256) void attn_split_kernel(
    const float* __restrict__ cache_k, const float* __restrict__ cache_v) {
    int blk = blockIdx.x;
    int pair = blk / NSPLIT, split = blk % NSPLIT;
    int b = pair >> 3, kv = pair & 7;
    int t0 = split * TCHUNK;
    int tid = threadIdx.x, lane = tid & 31, wid = tid >> 5;

    __shared__ float q_s[4][64];
    __shared__ float4 e_sT[TCHUNK];        // [t] -> exp(scores) for (g0..g3)
    __shared__ float red[4][8];
    __shared__ float o_part[4][4][64];     // [quarter][g][d]

    { // load + scale q
        int g = tid >> 6, d = tid & 63;
        q_s[g][d] = g_q[(size_t)b * DD + (kv * 4 + g) * 64 + d] * 0.125f;
    }
    __syncthreads();

    int c = lane & 7, p = lane >> 3;
    float qr[4][8];
#pragma unroll
    for (int g = 0; g < 4; g++)
#pragma unroll
        for (int j = 0; j < 8; j++) qr[g][j] = q_s[g][c * 8 + j];

    const float* kbase = cache_k + ((size_t)b * TSEQ * NKV + kv) * HDIM;
    const float* knew  = g_k + (size_t)(b * NKV + kv) * HDIM;

    // phase 1: exp(scores) -> smem; accumulate denominator inline
    float esum[4] = {0.f, 0.f, 0.f, 0.f};
#pragma unroll
    for (int it = 0; it < 4; it++) {
        int tl = it * 32 + wid * 4 + p;
        int t = t0 + tl;
        const float* krow = (t < TSEQ - 1) ? (kbase + (size_t)t * KVD) : knew;
        const float4* k4 = (const float4*)krow;
        float4 k0 = __ldcs(k4 + c * 2);
        float4 k1 = __ldcs(k4 + c * 2 + 1);
        float kv8[8] = {k0.x, k0.y, k0.z, k0.w, k1.x, k1.y, k1.z, k1.w};
        float a0 = 0.f, a1 = 0.f, a2 = 0.f, a3 = 0.f;
#pragma unroll
        for (int j = 0; j < 8; j++) {
            a0 += qr[0][j] * kv8[j];
            a1 += qr[1][j] * kv8[j];
            a2 += qr[2][j] * kv8[j];
            a3 += qr[3][j] * kv8[j];
        }
#pragma unroll
        for (int off = 1; off <= 4; off <<= 1) {
            a0 += __shfl_xor_sync(0xffffffffu, a0, off);
            a1 += __shfl_xor_sync(0xffffffffu, a1, off);
            a2 += __shfl_xor_sync(0xffffffffu, a2, off);
            a3 += __shfl_xor_sync(0xffffffffu, a3, off);
        }
        if (c == 0) {
            float4 e;
            e.x = __expf(a0); e.y = __expf(a1);
            e.z = __expf(a2); e.w = __expf(a3);
            e_sT[tl] = e;
            esum[0] += e.x; esum[1] += e.y; esum[2] += e.z; esum[3] += e.w;
        }
    }
#pragma unroll
    for (int g = 0; g < 4; g++) {
        esum[g] = warp_sum(esum[g]);
        if (lane == 0) red[g][wid] = esum[g];
    }
    __syncthreads();
    if (tid < 4) {
        float s = 0.f;
#pragma unroll
        for (int w = 0; w < 8; w++) s += red[tid][w];
        g_pl[blk * 4 + tid] = s;
    }

    // phase 3: PV — thread (quarter, d); each V element read once per CTA
    {
        int qq = tid >> 6, d = tid & 63;
        const float* vcol = cache_v + ((size_t)b * TSEQ * NKV + kv) * HDIM + d;
        const float* vnew = g_v + (size_t)(b * NKV + kv) * HDIM + d;
        float o0 = 0.f, o1 = 0.f, o2 = 0.f, o3 = 0.f;
        int tlb = qq * 32;
#pragma unroll 8
        for (int i = 0; i < 32; i++) {
            int tl = tlb + i;
            int t = t0 + tl;
            float v = (t < TSEQ - 1) ? __ldcs(vcol + (size_t)t * KVD) : *vnew;
            float4 pv = e_sT[tl];
            o0 += pv.x * v; o1 += pv.y * v; o2 += pv.z * v; o3 += pv.w * v;
        }
        o_part[qq][0][d] = o0;
        o_part[qq][1][d] = o1;
        o_part[qq][2][d] = o2;
        o_part[qq][3][d] = o3;
    }
    __syncthreads();
    {
        int g = tid >> 6, d = tid & 63;
        float sum = o_part[0][g][d] + o_part[1][g][d] +
                    o_part[2][g][d] + o_part[3][g][d];
        g_po[(size_t)blk * 256 + g * 64 + d] = sum;
    }
}

// combine split partials (pure sums — no max rescale needed)
__global__ __launch_bounds__(256) void attn_reduce_kernel() {
    int pair = blockIdx.x;
    int b = pair >> 3, kv = pair & 7;
    int tid = threadIdx.x, g = tid >> 6, d = tid & 63;
    float l = 0.f, o = 0.f;
#pragma unroll
    for (int s = 0; s < NSPLIT; s++) {
        int bs = pair * NSPLIT + s;
        l += g_pl[bs * 4 + g];
        o += g_po[(size_t)bs * 256 + g * 64 + d];
    }
    g_attn[(size_t)b * DD + (kv * 4 + g) * 64 + d] = o / l;
}

// ---------------- launch ----------------
extern "C" void kernel_launch(void* const* d_in, const int* in_sizes, int n_in,
                              void* d_out, int out_size) {
    const float* x         = (const float*)d_in[0];
    const float* freqs_cos = (const float*)d_in[1];
    const float* freqs_sin = (const float*)d_in[2];
    const float* cache_k   = (const float*)d_in[3];
    const float* cache_v   = (const float*)d_in[4];
    const float* wq_w      = (const float*)d_in[5];
    const float* wk_w      = (const float*)d_in[6];
    const float* wv_w      = (const float*)d_in[7];
    const float* wo_w      = (const float*)d_in[8];
    const float* w1_w      = (const float*)d_in[9];
    const float* w2_w      = (const float*)d_in[10];
    const float* w3_w      = (const float*)d_in[11];
    const float* attn_nw   = (const float*)d_in[12];
    const float* ffn_nw    = (const float*)d_in[13];
    float* out = (float*)d_out;

    rmsnorm_x_kernel<<<BB, 256>>>(x, attn_nw);
    gemv_qkv_kernel<<<3072 / 8, 256>>>(wq_w, wk_w, wv_w);
    rope_kernel<<<(BB * 48 * 32 + 255) / 256, 256>>>(freqs_cos, freqs_sin);
    attn_split_kernel<<<BB * NKV * NSPLIT, 256>>>(cache_k, cache_v);
    attn_reduce_kernel<<<BB * NKV, 256>>>();
    gemv_wo_kernel<<<DD / 8, 256>>>(wo_w, x);
    rmsnorm_h_kernel<<<BB, 256>>>(ffn_nw);
    gemv_w1_kernel<<<HIDDEN / 8, 256>>>(w1_w);
    gemv_w2_kernel<<<DD / 8, 256>>>(w2_w);
    gemv_w3fin_kernel<<<DD / 8, 256>>>(w3_w, out);
}